// round 2
// baseline (speedup 1.0000x reference)
#include <cuda_runtime.h>

#define NN_C   50000
#define DD_C   64
#define EE_C   800000
#define BB_C   50
#define NMAX_C 1000
#define CC_C   100

// ---------------- device scratch (no allocations allowed) ----------------
__device__ float g_xa[NN_C * DD_C];          // x @ W_ma[:64] + b_ma
__device__ float g_agg[NN_C * DD_C];         // segment_sum accumulator
__device__ float g_msgup[BB_C * CC_C * DD_C];// relu(attr1 @ W_mu + b_mu)
__device__ float g_aggup[NN_C * DD_C];       // nc1 @ msgup (B*NMAX == N rows)
__device__ float g_v[NN_C * 2 * DD_C];       // [relu(h1@Wua+b), relu(h2@Wuu+b)]

// ---------------- zero the scatter accumulator ----------------
__global__ __launch_bounds__(256) void zero_kernel(float* __restrict__ p, int n4) {
    float4 z = make_float4(0.f, 0.f, 0.f, 0.f);
    for (int i = blockIdx.x * blockDim.x + threadIdx.x; i < n4;
         i += gridDim.x * blockDim.x)
        ((float4*)p)[i] = z;
}

// ---------------- generic row-major [R,K] @ [K,64] (+bias, opt relu) -----
template <int K, int ROWS, bool RELU>
__global__ __launch_bounds__(256) void rowmm_kernel(
    const float* __restrict__ in, const float* __restrict__ W,
    const float* __restrict__ bias, float* __restrict__ out, int R)
{
    constexpr int KP = K + 4;  // pad: keeps rows 16B-aligned & banks spread
    __shared__ float sW[K * 64];
    __shared__ float sb[64];
    __shared__ __align__(16) float srow[8][ROWS][KP];

    int tid = threadIdx.x;
    for (int i = tid; i < K * 64; i += 256) sW[i] = W[i];
    if (tid < 64) sb[tid] = bias[tid];
    __syncthreads();

    int warp = tid >> 5, lane = tid & 31;
    int nw = gridDim.x * 8;
    int gw = blockIdx.x * 8 + warp;

    for (int base = gw * ROWS; base < R; base += nw * ROWS) {
        int nr = min(ROWS, R - base);
        const float4* ip = (const float4*)(in + (size_t)base * K);
        constexpr int NF4 = ROWS * K / 4;
#pragma unroll
        for (int t = 0; t < (NF4 + 31) / 32; t++) {
            int idx = lane + 32 * t;
            if (idx < nr * (K / 4)) {
                float4 val = ip[idx];
                int r = idx / (K / 4);
                int c = (idx & (K / 4 - 1)) * 4;
                *(float4*)&srow[warp][r][c] = val;
            }
        }
        __syncwarp();

        float a0[ROWS], a1[ROWS];
#pragma unroll
        for (int r = 0; r < ROWS; r++) { a0[r] = sb[lane]; a1[r] = sb[lane + 32]; }

#pragma unroll 4
        for (int k4 = 0; k4 < K / 4; k4++) {
            float4 rv[ROWS];
#pragma unroll
            for (int r = 0; r < ROWS; r++)
                rv[r] = *(const float4*)&srow[warp][r][k4 * 4];
#pragma unroll
            for (int kk = 0; kk < 4; kk++) {
                int k = k4 * 4 + kk;
                float w0 = sW[k * 64 + lane];
                float w1 = sW[k * 64 + lane + 32];
#pragma unroll
                for (int r = 0; r < ROWS; r++) {
                    float v = (&rv[r].x)[kk];
                    a0[r] += v * w0;
                    a1[r] += v * w1;
                }
            }
        }
#pragma unroll
        for (int r = 0; r < ROWS; r++)
            if (r < nr) {
                float o0 = a0[r], o1 = a1[r];
                if (RELU) { o0 = fmaxf(o0, 0.f); o1 = fmaxf(o1, 0.f); }
                out[(size_t)(base + r) * 64 + lane]      = o0;
                out[(size_t)(base + r) * 64 + lane + 32] = o1;
            }
        __syncwarp();
    }
}

// ---------------- edge kernel: msg = relu(xa[src] + e@Wb), scatter-add ---
__global__ __launch_bounds__(256) void edge_kernel(
    const float* __restrict__ e, const int* __restrict__ src,
    const int* __restrict__ dst, const float* __restrict__ Wb,
    const float* __restrict__ xa, float* __restrict__ agg, int E)
{
    __shared__ float sW[64 * 64];
    __shared__ __align__(16) float se[8][4][68];

    int tid = threadIdx.x;
    for (int i = tid; i < 64 * 64; i += 256) sW[i] = Wb[i];
    __syncthreads();

    int warp = tid >> 5, lane = tid & 31;
    int nw = gridDim.x * 8;
    int gw = blockIdx.x * 8 + warp;

    for (int base = gw * 4; base < E; base += nw * 4) {
        int ne = min(4, E - base);
        const float4* ep = (const float4*)(e + (size_t)base * 64);
#pragma unroll
        for (int t = 0; t < 2; t++) {
            int idx = lane + 32 * t;
            if (idx < ne * 16) {
                float4 v = ep[idx];
                int r = idx >> 4;
                int c = (idx & 15) << 2;
                *(float4*)&se[warp][r][c] = v;
            }
        }
        __syncwarp();

        float a0[4], a1[4];
#pragma unroll
        for (int r = 0; r < 4; r++) {
            int s = src[base + ((r < ne) ? r : 0)];
            a0[r] = xa[(size_t)s * 64 + lane];
            a1[r] = xa[(size_t)s * 64 + lane + 32];
        }

#pragma unroll 4
        for (int k4 = 0; k4 < 16; k4++) {
            float4 ev[4];
#pragma unroll
            for (int r = 0; r < 4; r++)
                ev[r] = *(const float4*)&se[warp][r][k4 * 4];
#pragma unroll
            for (int kk = 0; kk < 4; kk++) {
                int k = k4 * 4 + kk;
                float w0 = sW[k * 64 + lane];
                float w1 = sW[k * 64 + lane + 32];
#pragma unroll
                for (int r = 0; r < 4; r++) {
                    float v = (&ev[r].x)[kk];
                    a0[r] += v * w0;
                    a1[r] += v * w1;
                }
            }
        }
#pragma unroll
        for (int r = 0; r < 4; r++)
            if (r < ne) {
                int d = dst[base + r];
                atomicAdd(&agg[(size_t)d * 64 + lane],      fmaxf(a0[r], 0.f));
                atomicAdd(&agg[(size_t)d * 64 + lane + 32], fmaxf(a1[r], 0.f));
            }
        __syncwarp();
    }
}

// ---------------- pooling: agg_up[b] = nc1[b] @ msgup[b] ------------------
__global__ __launch_bounds__(256) void aggup_kernel(
    const float* __restrict__ nc1, const float* __restrict__ msgup,
    float* __restrict__ out)
{
    __shared__ float sM[CC_C * 64];
    __shared__ __align__(16) float sn[8][4][104];

    int b = blockIdx.x;
    int tid = threadIdx.x;
    for (int i = tid; i < CC_C * 64; i += 256)
        sM[i] = msgup[(size_t)b * CC_C * 64 + i];
    __syncthreads();

    int warp = tid >> 5, lane = tid & 31;
    int n0 = blockIdx.y * 32 + warp * 4;
    if (n0 >= NMAX_C) return;
    int ne = min(4, NMAX_C - n0);

    const float* srcp = nc1 + ((size_t)b * NMAX_C + n0) * CC_C;
    for (int i = lane; i < ne * CC_C; i += 32) {
        int r = i / CC_C, c = i - r * CC_C;
        sn[warp][r][c] = srcp[i];
    }
    __syncwarp();

    float a0[4] = {0.f, 0.f, 0.f, 0.f}, a1[4] = {0.f, 0.f, 0.f, 0.f};
#pragma unroll 5
    for (int k4 = 0; k4 < CC_C / 4; k4++) {
        float4 nv[4];
#pragma unroll
        for (int r = 0; r < 4; r++)
            nv[r] = *(const float4*)&sn[warp][r][k4 * 4];
#pragma unroll
        for (int kk = 0; kk < 4; kk++) {
            int k = k4 * 4 + kk;
            float w0 = sM[k * 64 + lane];
            float w1 = sM[k * 64 + lane + 32];
#pragma unroll
            for (int r = 0; r < 4; r++) {
                float v = (&nv[r].x)[kk];
                a0[r] += v * w0;
                a1[r] += v * w1;
            }
        }
    }
#pragma unroll
    for (int r = 0; r < 4; r++)
        if (r < ne) {
            size_t o = ((size_t)b * NMAX_C + n0 + r) * 64;
            out[o + lane]      = a0[r];
            out[o + lane + 32] = a1[r];
        }
}

// ---------------- pass A: v = [relu(h1@Wua+b), relu(h2@Wuu+b)] -----------
__global__ __launch_bounds__(256) void passA_kernel(
    const float* __restrict__ x, const float* __restrict__ agg,
    const float* __restrict__ aggup, const int* __restrict__ xidx,
    const float* __restrict__ eps1, const float* __restrict__ eps2,
    const float* __restrict__ Wua, const float* __restrict__ bua,
    const float* __restrict__ Wuu, const float* __restrict__ buu,
    float* __restrict__ v, int Nn)
{
    __shared__ float sWa[64 * 64];
    __shared__ float sWu[64 * 64];
    __shared__ float sba[64], sbu[64];
    __shared__ __align__(16) float sh[8][2][68];

    int tid = threadIdx.x;
    for (int i = tid; i < 4096; i += 256) { sWa[i] = Wua[i]; sWu[i] = Wuu[i]; }
    if (tid < 64) { sba[tid] = bua[tid]; sbu[tid] = buu[tid]; }
    __syncthreads();

    float c1 = 1.f + eps1[0];
    float c2 = 1.f + eps2[0];
    int warp = tid >> 5, lane = tid & 31;
    int nw = gridDim.x * 8;
    int gw = blockIdx.x * 8 + warp;

    for (int n = gw; n < Nn; n += nw) {
        float x0 = x[(size_t)n * 64 + lane];
        float x1 = x[(size_t)n * 64 + lane + 32];
        int up = xidx[n];
        sh[warp][0][lane]      = agg[(size_t)n * 64 + lane]       + c1 * x0;
        sh[warp][0][lane + 32] = agg[(size_t)n * 64 + lane + 32]  + c1 * x1;
        sh[warp][1][lane]      = aggup[(size_t)up * 64 + lane]      + c2 * x0;
        sh[warp][1][lane + 32] = aggup[(size_t)up * 64 + lane + 32] + c2 * x1;
        __syncwarp();

        float a0 = sba[lane], a1 = sba[lane + 32];
        float u0 = sbu[lane], u1 = sbu[lane + 32];
#pragma unroll 4
        for (int k4 = 0; k4 < 16; k4++) {
            float4 h1 = *(const float4*)&sh[warp][0][k4 * 4];
            float4 h2 = *(const float4*)&sh[warp][1][k4 * 4];
#pragma unroll
            for (int kk = 0; kk < 4; kk++) {
                int k = k4 * 4 + kk;
                float v1 = (&h1.x)[kk];
                float v2 = (&h2.x)[kk];
                a0 += v1 * sWa[k * 64 + lane];
                a1 += v1 * sWa[k * 64 + lane + 32];
                u0 += v2 * sWu[k * 64 + lane];
                u1 += v2 * sWu[k * 64 + lane + 32];
            }
        }
        size_t o = (size_t)n * 128;
        v[o + lane]           = fmaxf(a0, 0.f);
        v[o + lane + 32]      = fmaxf(a1, 0.f);
        v[o + 64 + lane]      = fmaxf(u0, 0.f);
        v[o + 64 + lane + 32] = fmaxf(u1, 0.f);
        __syncwarp();
    }
}

// ---------------- launch ----------------
extern "C" void kernel_launch(void* const* d_in, const int* in_sizes, int n_in,
                              void* d_out, int out_size)
{
    const float* x     = (const float*)d_in[0];
    const float* e     = (const float*)d_in[1];
    const int*   ei    = (const int*)d_in[2];
    const float* attr1 = (const float*)d_in[3];
    const float* nc1   = (const float*)d_in[4];
    const int*   xidx  = (const int*)d_in[5];
    const float* eps1  = (const float*)d_in[6];
    const float* eps2  = (const float*)d_in[7];
    const float* Wma   = (const float*)d_in[8];
    const float* bma   = (const float*)d_in[9];
    const float* Wmu   = (const float*)d_in[10];
    const float* bmu   = (const float*)d_in[11];
    const float* Wua   = (const float*)d_in[12];
    const float* bua   = (const float*)d_in[13];
    const float* Wuu   = (const float*)d_in[14];
    const float* buu   = (const float*)d_in[15];
    const float* Wc    = (const float*)d_in[16];
    const float* bc    = (const float*)d_in[17];
    float* out = (float*)d_out;

    int N = in_sizes[0] / 64;
    int E = in_sizes[2] / 2;

    float *p_xa, *p_agg, *p_msgup, *p_aggup, *p_v;
    cudaGetSymbolAddress((void**)&p_xa,    g_xa);
    cudaGetSymbolAddress((void**)&p_agg,   g_agg);
    cudaGetSymbolAddress((void**)&p_msgup, g_msgup);
    cudaGetSymbolAddress((void**)&p_aggup, g_aggup);
    cudaGetSymbolAddress((void**)&p_v,     g_v);

    // 1) zero the scatter accumulator
    zero_kernel<<<1024, 256>>>(p_agg, N * 64 / 4);

    // 2) xa = x @ W_ma[:64] + b_ma  (bias folded here, relu after edge add)
    {
        int blocks = (N + 31) / 32;
        rowmm_kernel<64, 4, false><<<blocks, 256>>>(x, Wma, bma, p_xa, N);
    }

    // 3) msg_up = relu(attr1 @ W_mu + b_mu)   (B*C rows)
    {
        int R = BB_C * CC_C;
        rowmm_kernel<64, 4, true><<<(R + 31) / 32, 256>>>(attr1, Wmu, bmu, p_msgup, R);
    }

    // 4) edge MLP + scatter-sum (dominant)
    edge_kernel<<<1184, 256>>>(e, ei, ei + E, Wma + 64 * 64, p_xa, p_agg, E);

    // 5) agg_up[b] = nc1[b] @ msg_up[b]
    aggup_kernel<<<dim3(BB_C, (NMAX_C + 31) / 32), 256>>>(nc1, p_msgup, p_aggup);

    // 6) v = [relu((agg+ (1+e1)x)@Wua+b), relu((aggup[idx]+(1+e2)x)@Wuu+b)]
    passA_kernel<<<1184, 256>>>(x, p_agg, p_aggup, xidx, eps1, eps2,
                                Wua, bua, Wuu, buu, p_v, N);

    // 7) out = v @ W_c + b_c   ([N,128] @ [128,64])
    rowmm_kernel<128, 2, false><<<1184, 256>>>(p_v, Wc, bc, out, N);
}